// round 4
// baseline (speedup 1.0000x reference)
#include <cuda_runtime.h>
#include <cstdint>

// ---------------------------------------------------------------------------
// Problem constants
// ---------------------------------------------------------------------------
#define N_NODES 500000
#define S_SAMPLE 100000
#define EQCAP 8192
#define OUT_C 256
#define IN_C 256

// Word-combine rule for the partitionable threefry path:
//   2 -> out0 ^ out1  (jax _threefry_random_bits_partitionable, bit_width 32)
//   1 -> out1 (low word)         [tested round 3: wrong]
//   0 -> out0 (high word)
#define TF_OUT_WORD 2

// libdevice accurate log (immune to fast-math logf substitution)
extern "C" __device__ float __nv_logf(float);

// ---------------------------------------------------------------------------
// Device scratch
// ---------------------------------------------------------------------------
__device__ unsigned g_keys[N_NODES];
__device__ unsigned char g_flag[N_NODES];
__device__ int g_sel[S_SAMPLE + 64];
__device__ int g_eqList[EQCAP];
__device__ unsigned g_hist[4][256];
__device__ unsigned g_thresh;
__device__ int g_counters[4];
#define C_SEL 0
#define C_EQ 1
#define C_REM 2

// ---------------------------------------------------------------------------
// Threefry-2x32, partitionable path (jax_threefry_partitionable=True):
// per element i (i < 2^32): counts1 = hi32(i) = 0, counts2 = lo32(i) = i,
// key = threefry_seed(42) = (0, 42).
// 32-bit draw = bits1 ^ bits2 (convert_element_type of the XOR).
// ---------------------------------------------------------------------------
__device__ __forceinline__ unsigned rotl32(unsigned x, int r) {
    return (x << r) | (x >> (32 - r));
}

__device__ __forceinline__ unsigned threefry_bits(unsigned i) {
    const unsigned ks0 = 0u;
    const unsigned ks1 = 42u;
    const unsigned ks2 = 0x1BD11BDAu ^ ks0 ^ ks1;
    unsigned x0 = 0u + ks0;   // hi32(count) = 0
    unsigned x1 = i + ks1;    // lo32(count) = i
#define TF_R4(a, b, c, d)                                   \
    x0 += x1; x1 = rotl32(x1, a); x1 ^= x0;                 \
    x0 += x1; x1 = rotl32(x1, b); x1 ^= x0;                 \
    x0 += x1; x1 = rotl32(x1, c); x1 ^= x0;                 \
    x0 += x1; x1 = rotl32(x1, d); x1 ^= x0;
    TF_R4(13, 15, 26, 6)  x0 += ks1; x1 += ks2 + 1u;
    TF_R4(17, 29, 16, 24) x0 += ks2; x1 += ks0 + 2u;
    TF_R4(13, 15, 26, 6)  x0 += ks0; x1 += ks1 + 3u;
    TF_R4(17, 29, 16, 24) x0 += ks1; x1 += ks2 + 4u;
    TF_R4(13, 15, 26, 6)  x0 += ks2; x1 += ks0 + 5u;
#undef TF_R4
#if TF_OUT_WORD == 2
    return x0 ^ x1;
#elif TF_OUT_WORD == 1
    return x1;
#else
    return x0;
#endif
}

// float -> order-preserving uint32 (ascending)
__device__ __forceinline__ unsigned f2key(float f) {
    unsigned b = __float_as_uint(f);
    return (b & 0x80000000u) ? ~b : (b | 0x80000000u);
}

// ---------------------------------------------------------------------------
// Selection kernels
// ---------------------------------------------------------------------------
__global__ void init_kernel() {
    int t = threadIdx.x;
    unsigned* h = (unsigned*)g_hist;
    for (int i = t; i < 4 * 256; i += 256) h[i] = 0;
    if (t == 0) {
        g_thresh = 0;
        g_counters[C_SEL] = 0;
        g_counters[C_EQ] = 0;
        g_counters[C_REM] = 0;
    }
}

__global__ void score_kernel(const float* __restrict__ imp) {
    int i = blockIdx.x * blockDim.x + threadIdx.x;
    if (i >= N_NODES) return;
    unsigned bits = threefry_bits((unsigned)i);
    float f = __uint_as_float((bits >> 9) | 0x3F800000u) - 1.0f;
    float u = f + 1.17549435e-38f;  // == max(tiny, f*(1-tiny)+tiny) in f32
    float g = -__nv_logf(-__nv_logf(u));
    float score = __nv_logf(imp[i]) + g;
    g_keys[i] = f2key(score);
}

__global__ void hist_kernel(int level) {
    __shared__ unsigned sh[256];
    int tid = threadIdx.x;
    sh[tid] = 0;
    __syncthreads();
    unsigned T = g_thresh;
    int shift = 32 - 8 * level;
    int stride = gridDim.x * blockDim.x;
    for (int i = blockIdx.x * blockDim.x + tid; i < N_NODES; i += stride) {
        unsigned k = g_keys[i];
        bool ok = (level == 0) || ((k >> shift) == (T >> shift));
        if (ok) atomicAdd(&sh[(k >> (shift - 8)) & 255u], 1u);
    }
    __syncthreads();
    if (sh[tid]) atomicAdd(&g_hist[level][tid], sh[tid]);
}

__global__ void pick_kernel(int level) {
    unsigned need = (level == 0) ? (unsigned)S_SAMPLE : (unsigned)g_counters[C_REM];
    unsigned cum = 0;
    int sel = 0;
    for (int b = 255; b >= 0; b--) {
        unsigned c = g_hist[level][b];
        if (cum + c >= need) { sel = b; break; }
        cum += c;
    }
    g_thresh |= ((unsigned)sel) << (24 - 8 * level);
    g_counters[C_REM] = (int)(need - cum);
}

__global__ void flag_kernel() {
    int i = blockIdx.x * blockDim.x + threadIdx.x;
    if (i >= N_NODES) return;
    unsigned k = g_keys[i];
    unsigned T = g_thresh;
    if (k > T) {
        g_flag[i] = 1;
        int p = atomicAdd(&g_counters[C_SEL], 1);
        if (p < S_SAMPLE + 64) g_sel[p] = i;
    } else if (k == T) {
        g_flag[i] = 0;
        int e = atomicAdd(&g_counters[C_EQ], 1);
        if (e < EQCAP) g_eqList[e] = i;
    } else {
        g_flag[i] = 0;
    }
}

__global__ void eq_pick_kernel() {
    // take the d lowest-index threshold-equal elements (lax.top_k tie-break)
    int n = g_counters[C_EQ];
    if (n > EQCAP) n = EQCAP;
    int d = g_counters[C_REM];
    for (int t = threadIdx.x; t < n; t += blockDim.x) {
        int idx = g_eqList[t];
        int rank = 0;
        for (int j = 0; j < n; j++) rank += (g_eqList[j] < idx) ? 1 : 0;
        if (rank < d) {
            g_flag[idx] = 1;
            int p = atomicAdd(&g_counters[C_SEL], 1);
            if (p < S_SAMPLE + 64) g_sel[p] = idx;
        }
    }
}

__global__ void zero_kernel(float* __restrict__ out) {
    int gw = (blockIdx.x * blockDim.x + threadIdx.x) >> 5;
    int lane = threadIdx.x & 31;
    int nw = (gridDim.x * blockDim.x) >> 5;
    float4 z = make_float4(0.f, 0.f, 0.f, 0.f);
    for (int row = gw; row < N_NODES; row += nw) {
        if (!g_flag[row]) {
            float4* p = (float4*)(out + (size_t)row * OUT_C);
            p[lane] = z;
            p[lane + 32] = z;
        }
    }
}

// ---------------------------------------------------------------------------
// GEMM: 64 selected rows x 256 cols per block, 8x8 register tile per thread,
// packed fma.rn.f32x2 (validated bit-identical to fmaf path in rounds 1/2)
// ---------------------------------------------------------------------------
#define FMA2(d, a, b) \
    asm("fma.rn.f32x2 %0, %1, %2, %0;" : "+l"(d) : "l"(a), "l"(b))
#define DUP2(d, s) \
    asm("mov.b64 %0, {%1, %1};" : "=l"(d) : "r"(__float_as_uint(s)))

__global__ void __launch_bounds__(256) gemm_kernel(
    const float* __restrict__ x, const float* __restrict__ w,
    const float* __restrict__ bias, float* __restrict__ out) {
    __shared__ float xs[32][64];      // [k][row]
    __shared__ float ws[32][256];     // [k][col]
    __shared__ int rows_s[64];

    int tid = threadIdx.x;
    int r0 = blockIdx.x * 64;
    if (tid < 64) {
        int rr = r0 + tid;
        rows_s[tid] = g_sel[(rr < S_SAMPLE) ? rr : r0];
    }
    __syncthreads();

    int tr = tid >> 5;   // 0..7  -> row group of 8
    int tc = tid & 31;   // 0..31 -> col group of 8

    unsigned long long acc[8][4];
#pragma unroll
    for (int r = 0; r < 8; r++)
#pragma unroll
        for (int c = 0; c < 4; c++) acc[r][c] = 0ull;

    for (int k0 = 0; k0 < IN_C; k0 += 32) {
        if (k0) __syncthreads();
#pragma unroll
        for (int it = 0; it < 2; it++) {
            int j = tid + it * 256;
            int r = j >> 3;
            int c4 = (j & 7) * 4;
            const float4 v =
                *(const float4*)&x[(size_t)rows_s[r] * IN_C + k0 + c4];
            xs[c4 + 0][r] = v.x;
            xs[c4 + 1][r] = v.y;
            xs[c4 + 2][r] = v.z;
            xs[c4 + 3][r] = v.w;
        }
#pragma unroll
        for (int it = 0; it < 8; it++) {
            int j = tid + it * 256;
            int kr = j >> 6;
            int c4 = (j & 63) * 4;
            *(float4*)&ws[kr][c4] = *(const float4*)&w[(size_t)(k0 + kr) * OUT_C + c4];
        }
        __syncthreads();
#pragma unroll 8
        for (int kk = 0; kk < 32; kk++) {
            float4 xa = *(const float4*)&xs[kk][tr * 8];
            float4 xb = *(const float4*)&xs[kk][tr * 8 + 4];
            ulonglong2 w01 = *(const ulonglong2*)&ws[kk][tc * 8];
            ulonglong2 w23 = *(const ulonglong2*)&ws[kk][tc * 8 + 4];
            unsigned long long xd[8];
            DUP2(xd[0], xa.x); DUP2(xd[1], xa.y);
            DUP2(xd[2], xa.z); DUP2(xd[3], xa.w);
            DUP2(xd[4], xb.x); DUP2(xd[5], xb.y);
            DUP2(xd[6], xb.z); DUP2(xd[7], xb.w);
#pragma unroll
            for (int r = 0; r < 8; r++) {
                FMA2(acc[r][0], xd[r], w01.x);
                FMA2(acc[r][1], xd[r], w01.y);
                FMA2(acc[r][2], xd[r], w23.x);
                FMA2(acc[r][3], xd[r], w23.y);
            }
        }
    }

    const float scale = (float)N_NODES / (float)S_SAMPLE;  // 5.0
    float bb[8];
#pragma unroll
    for (int c = 0; c < 8; c++) bb[c] = bias[tc * 8 + c];

#pragma unroll
    for (int r = 0; r < 8; r++) {
        int lr = tr * 8 + r;
        int rowid = r0 + lr;
        if (rowid < S_SAMPLE) {
            int g = rows_s[lr];
            float o[8];
#pragma unroll
            for (int cp = 0; cp < 4; cp++) {
                o[2 * cp + 0] = __uint_as_float((unsigned)(acc[r][cp] & 0xFFFFFFFFull));
                o[2 * cp + 1] = __uint_as_float((unsigned)(acc[r][cp] >> 32));
            }
#pragma unroll
            for (int c = 0; c < 8; c++) o[c] = (o[c] + bb[c]) * scale;
            float* dst = out + (size_t)g * OUT_C + tc * 8;
            *(float4*)dst = make_float4(o[0], o[1], o[2], o[3]);
            *(float4*)(dst + 4) = make_float4(o[4], o[5], o[6], o[7]);
        }
    }
}

// ---------------------------------------------------------------------------
// Launch — inputs dispatched by element count (robust to metadata ordering):
//   x: 128,000,000   weight: 65,536   bias: 256   importance: 500,000
//   edge_index: 16,000,000 (unused)
// ---------------------------------------------------------------------------
extern "C" void kernel_launch(void* const* d_in, const int* in_sizes, int n_in,
                              void* d_out, int out_size) {
    const float* x = nullptr;
    const float* w = nullptr;
    const float* bias = nullptr;
    const float* imp = nullptr;
    for (int i = 0; i < n_in; i++) {
        switch (in_sizes[i]) {
            case 128000000: x = (const float*)d_in[i]; break;
            case 65536:     w = (const float*)d_in[i]; break;
            case 256:       bias = (const float*)d_in[i]; break;
            case 500000:    imp = (const float*)d_in[i]; break;
            default: break;  // edge_index unused
        }
    }
    float* out = (float*)d_out;
    (void)out_size;

    init_kernel<<<1, 256>>>();
    score_kernel<<<(N_NODES + 255) / 256, 256>>>(imp);
    for (int l = 0; l < 4; l++) {
        hist_kernel<<<512, 256>>>(l);
        pick_kernel<<<1, 1>>>(l);
    }
    flag_kernel<<<(N_NODES + 255) / 256, 256>>>();
    eq_pick_kernel<<<1, 256>>>();
    zero_kernel<<<1024, 256>>>(out);
    gemm_kernel<<<(S_SAMPLE + 63) / 64, 256>>>(x, w, bias, out);
}

// round 6
// speedup vs baseline: 1.9893x; 1.9893x over previous
#include <cuda_runtime.h>
#include <cuda_fp16.h>
#include <cstdint>

// ---------------------------------------------------------------------------
// Problem constants
// ---------------------------------------------------------------------------
#define N_NODES 500000
#define S_SAMPLE 100000
#define EQCAP 8192
#define OUT_C 256
#define IN_C 256
#define M_TILE 64
#define NBLK ((S_SAMPLE + M_TILE - 1) / M_TILE)   // 1563

// libdevice accurate log (immune to fast-math logf substitution)
extern "C" __device__ float __nv_logf(float);

// ---------------------------------------------------------------------------
// Device scratch
// ---------------------------------------------------------------------------
__device__ unsigned g_keys[N_NODES];
__device__ unsigned char g_flag[N_NODES];
__device__ int g_sel[S_SAMPLE + M_TILE];
__device__ int g_eqList[EQCAP];
__device__ unsigned g_hist[4][256];
__device__ unsigned g_thresh;
__device__ int g_counters[4];
__device__ unsigned g_done[4];
__device__ unsigned g_wh[32768];   // w as f16 pairs, [k][n] row-major (n contiguous)
#define C_SEL 0
#define C_EQ 1
#define C_REM 2

// ---------------------------------------------------------------------------
// Threefry-2x32, partitionable: x0 = 0, x1 = i, key = (0,42); draw = out0 ^ out1
// (validated exact in round 4)
// ---------------------------------------------------------------------------
__device__ __forceinline__ unsigned rotl32(unsigned x, int r) {
    return (x << r) | (x >> (32 - r));
}
__device__ __forceinline__ unsigned threefry_bits(unsigned i) {
    const unsigned ks0 = 0u, ks1 = 42u;
    const unsigned ks2 = 0x1BD11BDAu ^ ks0 ^ ks1;
    unsigned x0 = 0u + ks0;
    unsigned x1 = i + ks1;
#define TF_R4(a, b, c, d)                                   \
    x0 += x1; x1 = rotl32(x1, a); x1 ^= x0;                 \
    x0 += x1; x1 = rotl32(x1, b); x1 ^= x0;                 \
    x0 += x1; x1 = rotl32(x1, c); x1 ^= x0;                 \
    x0 += x1; x1 = rotl32(x1, d); x1 ^= x0;
    TF_R4(13, 15, 26, 6)  x0 += ks1; x1 += ks2 + 1u;
    TF_R4(17, 29, 16, 24) x0 += ks2; x1 += ks0 + 2u;
    TF_R4(13, 15, 26, 6)  x0 += ks0; x1 += ks1 + 3u;
    TF_R4(17, 29, 16, 24) x0 += ks1; x1 += ks2 + 4u;
    TF_R4(13, 15, 26, 6)  x0 += ks2; x1 += ks0 + 5u;
#undef TF_R4
    return x0 ^ x1;
}
__device__ __forceinline__ unsigned f2key(float f) {
    unsigned b = __float_as_uint(f);
    return (b & 0x80000000u) ? ~b : (b | 0x80000000u);
}

// ---------------------------------------------------------------------------
// Parallel byte-pick (256 threads, suffix scan) — runs in tail block
// ---------------------------------------------------------------------------
__device__ void pick_parallel(int level, unsigned* suf) {
    int t = threadIdx.x;
    suf[t] = g_hist[level][t];
    __syncthreads();
#pragma unroll
    for (int off = 1; off < 256; off <<= 1) {
        unsigned v = (t + off < 256) ? suf[t + off] : 0u;
        __syncthreads();
        suf[t] += v;
        __syncthreads();
    }
    unsigned need = (level == 0) ? (unsigned)S_SAMPLE : (unsigned)g_counters[C_REM];
    unsigned above = (t < 255) ? suf[t + 1] : 0u;   // keys strictly above bin t
    if (suf[t] >= need && above < need) {
        g_thresh |= ((unsigned)t) << (24 - 8 * level);
        g_counters[C_REM] = (int)(need - above);
        __threadfence();
    }
    __syncthreads();
}

// ---------------------------------------------------------------------------
// Kernels
// ---------------------------------------------------------------------------
__global__ void init_kernel() {
    int t = threadIdx.x;
    unsigned* h = (unsigned*)g_hist;
    for (int i = t; i < 4 * 256; i += 256) h[i] = 0;
    if (t < 4) { g_counters[t] = 0; g_done[t] = 0; }
    if (t == 0) g_thresh = 0;
}

// w[k][n] f32 -> f16 pairs, same [k][n] layout
__global__ void prep_w_kernel(const float* __restrict__ w) {
    int t = blockIdx.x * blockDim.x + threadIdx.x;  // 32768
    if (t >= 32768) return;
    float2 v = ((const float2*)w)[t];
    __half2 h = __floats2half2_rn(v.x, v.y);
    g_wh[t] = *(unsigned*)&h;
}

// score + level-0 histogram + fused pick0 (tail block)
__global__ void score_kernel(const float* __restrict__ imp) {
    __shared__ unsigned sh[256];
    __shared__ unsigned is_last;
    int tid = threadIdx.x;
    sh[tid] = 0;
    if (tid == 0) is_last = 0;
    __syncthreads();
    int i = blockIdx.x * blockDim.x + tid;
    if (i < N_NODES) {
        unsigned bits = threefry_bits((unsigned)i);
        float f = __uint_as_float((bits >> 9) | 0x3F800000u) - 1.0f;
        float u = f + 1.17549435e-38f;
        float g = -__nv_logf(-__nv_logf(u));
        unsigned k = f2key(__nv_logf(imp[i]) + g);
        g_keys[i] = k;
        atomicAdd(&sh[k >> 24], 1u);
    }
    __syncthreads();
    if (sh[tid]) atomicAdd(&g_hist[0][tid], sh[tid]);
    __threadfence();
    __syncthreads();
    if (tid == 0) {
        unsigned old = atomicAdd(&g_done[0], 1u);
        if (old == gridDim.x - 1) is_last = 1;
    }
    __syncthreads();
    if (is_last) pick_parallel(0, sh);
}

// hist levels 1..3 + fused pick (tail block)
__global__ void hist_kernel(int level) {
    __shared__ unsigned sh[256];
    __shared__ unsigned is_last;
    int tid = threadIdx.x;
    sh[tid] = 0;
    if (tid == 0) is_last = 0;
    __syncthreads();
    unsigned T = g_thresh;
    int shift = 32 - 8 * level;
    int stride = gridDim.x * blockDim.x;
    for (int i = blockIdx.x * blockDim.x + tid; i < N_NODES; i += stride) {
        unsigned k = g_keys[i];
        if ((k >> shift) == (T >> shift))
            atomicAdd(&sh[(k >> (shift - 8)) & 255u], 1u);
    }
    __syncthreads();
    if (sh[tid]) atomicAdd(&g_hist[level][tid], sh[tid]);
    __threadfence();
    __syncthreads();
    if (tid == 0) {
        unsigned old = atomicAdd(&g_done[level], 1u);
        if (old == gridDim.x - 1) is_last = 1;
    }
    __syncthreads();
    if (is_last) pick_parallel(level, sh);
}

__global__ void flag_kernel() {
    int i = blockIdx.x * blockDim.x + threadIdx.x;
    if (i >= N_NODES) return;
    unsigned k = g_keys[i];
    unsigned T = g_thresh;
    if (k > T) {
        g_flag[i] = 1;
        int p = atomicAdd(&g_counters[C_SEL], 1);
        if (p < S_SAMPLE + M_TILE) g_sel[p] = i;
    } else if (k == T) {
        g_flag[i] = 0;
        int e = atomicAdd(&g_counters[C_EQ], 1);
        if (e < EQCAP) g_eqList[e] = i;
    } else {
        g_flag[i] = 0;
    }
}

__global__ void eq_pick_kernel() {
    int n = g_counters[C_EQ];
    if (n > EQCAP) n = EQCAP;
    int d = g_counters[C_REM];
    for (int t = threadIdx.x; t < n; t += blockDim.x) {
        int idx = g_eqList[t];
        int rank = 0;
        for (int j = 0; j < n; j++) rank += (g_eqList[j] < idx) ? 1 : 0;
        if (rank < d) {
            g_flag[idx] = 1;
            int p = atomicAdd(&g_counters[C_SEL], 1);
            if (p < S_SAMPLE + M_TILE) g_sel[p] = idx;
        }
    }
}

__global__ void zero_kernel(float* __restrict__ out) {
    int gw = (blockIdx.x * blockDim.x + threadIdx.x) >> 5;
    int lane = threadIdx.x & 31;
    int nw = (gridDim.x * blockDim.x) >> 5;
    float4 z = make_float4(0.f, 0.f, 0.f, 0.f);
    for (int row = gw; row < N_NODES; row += nw) {
        if (!g_flag[row]) {
            float4* p = (float4*)(out + (size_t)row * OUT_C);
            p[lane] = z;
            p[lane + 32] = z;
        }
    }
}

// ---------------------------------------------------------------------------
// HMMA GEMM: M=64 gathered rows x N=256, K=256 in 32-chunks.
// 8 warps: warp w -> rows [(w&1)*32, +32), cols [(w>>1)*64, +64).
// Each warp: 2 m-tiles x 8 n-tiles of mma.m16n8k16 (f16 in, f32 accum).
// ---------------------------------------------------------------------------
#define A_STRIDE 40    // halves; 80B rows -> bank step 20, conflict-free
#define B_STRIDE 264   // halves; 528B rows -> bank step 4, conflict-free

__device__ __forceinline__ uint32_t smem_u32(const void* p) {
    uint32_t a;
    asm("{ .reg .u64 t; cvta.to.shared.u64 t, %1; cvt.u32.u64 %0, t; }"
        : "=r"(a) : "l"(p));
    return a;
}

__global__ void __launch_bounds__(256, 2) gemm_kernel(
    const float* __restrict__ x, const float* __restrict__ bias,
    float* __restrict__ out) {
    __shared__ __align__(16) __half As[M_TILE * A_STRIDE];   // 5120 B
    __shared__ __align__(16) __half Bs[32 * B_STRIDE];       // 16896 B
    __shared__ int rows_s[M_TILE];

    int tid = threadIdx.x;
    int wid = tid >> 5;
    int lane = tid & 31;
    int r0 = blockIdx.x * M_TILE;

    if (tid < M_TILE) {
        int rr = r0 + tid;
        rows_s[tid] = g_sel[(rr < S_SAMPLE) ? rr : r0];
    }
    __syncthreads();

    int m_half = wid & 1;          // 0/1 -> row base 0/32
    int n_quad = wid >> 1;         // 0..3 -> col base 0/64/128/192

    float acc[2][8][4];
#pragma unroll
    for (int mt = 0; mt < 2; mt++)
#pragma unroll
        for (int nt = 0; nt < 8; nt++)
#pragma unroll
            for (int q = 0; q < 4; q++) acc[mt][nt][q] = 0.f;

    // A-load mapping: thread -> (row = tid/4, part = tid%4 -> 8 floats)
    int a_row = tid >> 2;
    int a_part = (tid & 3) * 8;
    // B-load mapping: thread -> (krow = tid/8, seg = tid%8 -> 32 halves = 4 uint4)
    int b_krow = tid >> 3;
    int b_seg = (tid & 7) * 32;

    const uint32_t As_base = smem_u32(As);
    const uint32_t Bs_base = smem_u32(Bs);

    for (int k0 = 0; k0 < IN_C; k0 += 32) {
        if (k0) __syncthreads();
        // A tile: gather 64 rows x 32 k f32 -> f16
        {
            const float4* src =
                (const float4*)(x + (size_t)rows_s[a_row] * IN_C + k0 + a_part);
            float4 v0 = src[0];
            float4 v1 = src[1];
            __half2 h0 = __floats2half2_rn(v0.x, v0.y);
            __half2 h1 = __floats2half2_rn(v0.z, v0.w);
            __half2 h2 = __floats2half2_rn(v1.x, v1.y);
            __half2 h3 = __floats2half2_rn(v1.z, v1.w);
            unsigned* dst = (unsigned*)&As[a_row * A_STRIDE + a_part];
            dst[0] = *(unsigned*)&h0;
            dst[1] = *(unsigned*)&h1;
            dst[2] = *(unsigned*)&h2;
            dst[3] = *(unsigned*)&h3;
        }
        // B tile: 32 k-rows x 256 n halves from prepped w
        {
            const uint4* src = (const uint4*)&g_wh[(k0 + b_krow) * 128 + b_seg / 2];
            uint4* dst = (uint4*)&Bs[b_krow * B_STRIDE + b_seg];
            dst[0] = src[0];
            dst[1] = src[1];
            dst[2] = src[2];
            dst[3] = src[3];
        }
        __syncthreads();

#pragma unroll
        for (int ks = 0; ks < 2; ks++) {
            // A fragments: 2 m-tiles, ldmatrix x4
            uint32_t af[2][4];
#pragma unroll
            for (int mt = 0; mt < 2; mt++) {
                int row = m_half * 32 + mt * 16 + (lane & 15);
                int col = ks * 16 + (lane >> 4) * 8;
                uint32_t addr = As_base + (row * A_STRIDE + col) * 2;
                asm volatile(
                    "ldmatrix.sync.aligned.m8n8.x4.shared.b16 {%0,%1,%2,%3}, [%4];"
                    : "=r"(af[mt][0]), "=r"(af[mt][1]),
                      "=r"(af[mt][2]), "=r"(af[mt][3]) : "r"(addr));
            }
            // B fragments: 8 n-tiles, ldmatrix x2 trans
            uint32_t bf[8][2];
#pragma unroll
            for (int nt = 0; nt < 8; nt++) {
                int krow = ks * 16 + (lane & 15);
                int ncol = n_quad * 64 + nt * 8;
                uint32_t addr = Bs_base + (krow * B_STRIDE + ncol) * 2;
                asm volatile(
                    "ldmatrix.sync.aligned.m8n8.x2.trans.shared.b16 {%0,%1}, [%2];"
                    : "=r"(bf[nt][0]), "=r"(bf[nt][1]) : "r"(addr));
            }
#pragma unroll
            for (int mt = 0; mt < 2; mt++)
#pragma unroll
                for (int nt = 0; nt < 8; nt++) {
                    asm volatile(
                        "mma.sync.aligned.m16n8k16.row.col.f32.f16.f16.f32 "
                        "{%0,%1,%2,%3}, {%4,%5,%6,%7}, {%8,%9}, {%0,%1,%2,%3};"
                        : "+f"(acc[mt][nt][0]), "+f"(acc[mt][nt][1]),
                          "+f"(acc[mt][nt][2]), "+f"(acc[mt][nt][3])
                        : "r"(af[mt][0]), "r"(af[mt][1]),
                          "r"(af[mt][2]), "r"(af[mt][3]),
                          "r"(bf[nt][0]), "r"(bf[nt][1]));
                }
        }
    }

    // epilogue: (acc + bias) * 5, scatter to out rows
    const float scale = 5.0f;
    int qr = lane >> 2;            // 0..7
    int qc = (lane & 3) * 2;       // 0,2,4,6
#pragma unroll
    for (int mt = 0; mt < 2; mt++) {
        int lrow_lo = m_half * 32 + mt * 16 + qr;
        int g_lo = rows_s[lrow_lo];
        int g_hi = rows_s[lrow_lo + 8];
        float* row_lo = out + (size_t)g_lo * OUT_C;
        float* row_hi = out + (size_t)g_hi * OUT_C;
#pragma unroll
        for (int nt = 0; nt < 8; nt++) {
            int col = n_quad * 64 + nt * 8 + qc;
            float b0 = bias[col], b1 = bias[col + 1];
            *(float2*)(row_lo + col) = make_float2(
                (acc[mt][nt][0] + b0) * scale, (acc[mt][nt][1] + b1) * scale);
            *(float2*)(row_hi + col) = make_float2(
                (acc[mt][nt][2] + b0) * scale, (acc[mt][nt][3] + b1) * scale);
        }
    }
}

// ---------------------------------------------------------------------------
// Launch
// ---------------------------------------------------------------------------
extern "C" void kernel_launch(void* const* d_in, const int* in_sizes, int n_in,
                              void* d_out, int out_size) {
    const float* x = nullptr;
    const float* w = nullptr;
    const float* bias = nullptr;
    const float* imp = nullptr;
    for (int i = 0; i < n_in; i++) {
        switch (in_sizes[i]) {
            case 128000000: x = (const float*)d_in[i]; break;
            case 65536:     w = (const float*)d_in[i]; break;
            case 256:       bias = (const float*)d_in[i]; break;
            case 500000:    imp = (const float*)d_in[i]; break;
            default: break;  // edge_index unused
        }
    }
    float* out = (float*)d_out;
    (void)out_size;

    init_kernel<<<1, 256>>>();
    prep_w_kernel<<<128, 256>>>(w);
    score_kernel<<<(N_NODES + 255) / 256, 256>>>(imp);
    for (int l = 1; l < 4; l++) hist_kernel<<<512, 256>>>(l);
    flag_kernel<<<(N_NODES + 255) / 256, 256>>>();
    eq_pick_kernel<<<1, 256>>>();
    zero_kernel<<<1024, 256>>>(out);
    gemm_kernel<<<NBLK, 256>>>(x, bias, out);
}